// round 6
// baseline (speedup 1.0000x reference)
#include <cuda_runtime.h>
#include <cstdint>

#define B_    32
#define T_    512
#define D_    512
#define H_    512
#define FOURH 2048
#define NCTA  64          // CTAs per direction

typedef unsigned long long ull;

// ---- scratch ----
__device__ float g_xp[2][(size_t)B_ * T_ * FOURH];   // input projections
__device__ float g_h[2][2][H_ * B_];                 // h state, TRANSPOSED [j][b]
__device__ unsigned g_flag[2][NCTA];                 // published-step counters

__device__ __forceinline__ float sigm(float x) { return 1.f / (1.f + __expf(-x)); }
__device__ __forceinline__ float tanh_(float x) { return 2.f / (1.f + __expf(-2.f * x)) - 1.f; }

__device__ __forceinline__ ull fma2(ull a, ull b, ull c) {
    ull d;
    asm("fma.rn.f32x2 %0, %1, %2, %3;" : "=l"(d) : "l"(a), "l"(b), "l"(c));
    return d;
}
union F2U { ull u; float2 f; };
__device__ __forceinline__ float2 u2f(ull v) { F2U x; x.u = v; return x.f; }

__device__ __forceinline__ unsigned ld_acquire(const unsigned* p) {
    unsigned v;
    asm volatile("ld.global.acquire.gpu.u32 %0, [%1];" : "=r"(v) : "l"(p));
    return v;
}
__device__ __forceinline__ void st_relaxed(unsigned* p, unsigned v) {
    asm volatile("st.global.relaxed.gpu.u32 [%0], %1;" :: "l"(p), "r"(v));
}

// ---------------------------------------------------------------------------
// Flag reset — runs before lstm each replay (flags must start at 0).
// ---------------------------------------------------------------------------
__global__ void reset_flags() {
    if (threadIdx.x < 2 * NCTA)
        ((unsigned*)g_flag)[threadIdx.x] = 0;
}

// ---------------------------------------------------------------------------
// Phase 1: xp GEMM — unchanged (controlled variable).
// ---------------------------------------------------------------------------
__global__ __launch_bounds__(256, 2) void gemm_xp(
    const float* __restrict__ x,
    const float* __restrict__ Wfw, const float* __restrict__ bfw,
    const float* __restrict__ Wbw, const float* __restrict__ bbw)
{
    const int dir = blockIdx.z;
    const float* __restrict__ Wd = dir ? Wbw : Wfw;
    const float* __restrict__ bd = dir ? bbw : bfw;
    float* __restrict__ C = g_xp[dir];

    __shared__ float As[2][8][256];
    __shared__ float Bs[2][8][128];

    const int tid = threadIdx.x;
    const int m0 = blockIdx.y * 128;
    const int n0 = blockIdx.x * 128;
    const int tx = tid & 15;
    const int ty = tid >> 4;

    const int arow = tid >> 1;
    const int ak4  = (tid & 1) * 4;
    const int bk = tid >> 5;
    const int bn = (tid & 31) * 4;

    const float* Ap = x  + (size_t)(m0 + arow) * D_ + ak4;
    const float* Bp = Wd + (size_t)bk * FOURH + n0 + bn;

    ull acc[8][4];
#pragma unroll
    for (int i = 0; i < 8; i++)
#pragma unroll
        for (int j = 0; j < 4; j++) acc[i][j] = 0ull;

    float4 av = *(const float4*)(Ap);
    float4 bv = *(const float4*)(Bp);

    for (int k0 = 0; k0 < D_; k0 += 8) {
        const int buf = (k0 >> 3) & 1;
        *(float2*)&As[buf][ak4 + 0][2 * arow] = make_float2(av.x, av.x);
        *(float2*)&As[buf][ak4 + 1][2 * arow] = make_float2(av.y, av.y);
        *(float2*)&As[buf][ak4 + 2][2 * arow] = make_float2(av.z, av.z);
        *(float2*)&As[buf][ak4 + 3][2 * arow] = make_float2(av.w, av.w);
        *(float4*)&Bs[buf][bk][bn] = bv;
        __syncthreads();

        if (k0 + 8 < D_) {
            av = *(const float4*)(Ap + k0 + 8);
            bv = *(const float4*)(Bp + (size_t)(k0 + 8) * FOURH);
        }

#pragma unroll
        for (int kk = 0; kk < 8; kk++) {
            const ulonglong2* ap2 = (const ulonglong2*)&As[buf][kk][ty * 16];
            const ulonglong2* bp2 = (const ulonglong2*)&Bs[buf][kk][tx * 8];
            ulonglong2 a01 = ap2[0], a23 = ap2[1], a45 = ap2[2], a67 = ap2[3];
            ulonglong2 b01 = bp2[0], b23 = bp2[1];
            ull aa[8] = {a01.x, a01.y, a23.x, a23.y, a45.x, a45.y, a67.x, a67.y};
            ull bb[4] = {b01.x, b01.y, b23.x, b23.y};
#pragma unroll
            for (int i = 0; i < 8; i++)
#pragma unroll
                for (int j = 0; j < 4; j++)
                    acc[i][j] = fma2(aa[i], bb[j], acc[i][j]);
        }
    }
    __syncthreads();

    float bias[8];
#pragma unroll
    for (int j = 0; j < 8; j++) bias[j] = bd[n0 + tx * 8 + j];

#pragma unroll
    for (int i = 0; i < 8; i++) {
        const size_t row = (size_t)(m0 + ty * 8 + i);
        float* cp = C + row * FOURH + n0 + tx * 8;
        float2 c0 = u2f(acc[i][0]), c1 = u2f(acc[i][1]);
        float2 c2 = u2f(acc[i][2]), c3 = u2f(acc[i][3]);
        float4 o0, o1;
        o0.x = c0.x + bias[0]; o0.y = c0.y + bias[1];
        o0.z = c1.x + bias[2]; o0.w = c1.y + bias[3];
        o1.x = c2.x + bias[4]; o1.y = c2.y + bias[5];
        o1.z = c3.x + bias[6]; o1.w = c3.y + bias[7];
        *(float4*)(cp + 0) = o0;
        *(float4*)(cp + 4) = o1;
    }
}

// ---------------------------------------------------------------------------
// Phase 2: persistent LSTM, barrier-free dataflow via per-slice flags.
// Each CTA publishes its 8-row h slice + flag; consumers copy each slice as
// its flag lands (acquire-poll), overlapping straggler waits with copies.
// Matvec unchanged from R4 (W-dup FFMA2, FMA-bound).
// ---------------------------------------------------------------------------
#define W2_FLOATS  (512 * 64)          // 32768 (duplicated W)
#define H_FLOATS   (512 * 32)          // 16384
#define RED_STRIDE 34
#define NSPLIT     8
#define REDC(ks, c, b) ((((ks) * 32 + (c)) * RED_STRIDE) + (b))
#define SMEM_BYTES ((W2_FLOATS + H_FLOATS + NSPLIT * 32 * RED_STRIDE) * 4)

__global__ __launch_bounds__(512) void lstm_kernel(
    const float* __restrict__ Wfw, const float* __restrict__ Wbw,
    float* __restrict__ out)
{
    extern __shared__ float sm[];
    float* Wsh2 = sm;                         // [k][64] : k*64 + 2c (dup pairs)
    float* hsh  = sm + W2_FLOATS;             // [k][32] : k*32 + b
    float* red  = sm + W2_FLOATS + H_FLOATS;  // [ks][c][34]

    const int tid = threadIdx.x;
    const int dir = blockIdx.x / NCTA;
    const int cta = blockIdx.x % NCTA;
    const int j0  = cta * 8;
    const float* __restrict__ W  = dir ? Wbw : Wfw;
    const float* __restrict__ xp = g_xp[dir];

    // Prologue: Wh slice -> smem duplicated pairs. c = gate*8 + jj.
    for (int idx = tid; idx < H_FLOATS; idx += 512) {
        const int k = idx >> 5, c = idx & 31;
        const int gate = c >> 3, jj = c & 7;
        const float v = W[(size_t)(D_ + k) * FOURH + gate * H_ + j0 + jj];
        Wsh2[k * 64 + 2 * c]     = v;
        Wsh2[k * 64 + 2 * c + 1] = v;
    }

    const int warp = tid >> 5, lane = tid & 31;
    // matvec roles: tid = ks*64 + cg*8 + bq
    const int bq = tid & 7;
    const int cg = (tid >> 3) & 7;
    const int ks = tid >> 6;
    // gate roles (first 256 threads)
    const int b_g = tid >> 3, jj_g = tid & 7;
    const bool gate_thread = (tid < 256);

    float cst = 0.f;
    __syncthreads();

    for (int s = 0; s < T_; s++) {
        const int t = dir ? (T_ - 1 - s) : s;

        float x0 = 0, x1 = 0, x2 = 0, x3 = 0;
        if (gate_thread) {
            const size_t xrow = ((size_t)b_g * T_ + t) * FOURH + j0 + jj_g;
            x0 = __ldg(xp + xrow + 0 * H_);
            x1 = __ldg(xp + xrow + 1 * H_);
            x2 = __ldg(xp + xrow + 2 * H_);
            x3 = __ldg(xp + xrow + 3 * H_);
        }

        if (s > 0) {
            // per-slice acquire-poll + copy: warp w owns slices 4w..4w+3.
            const float* hsrc = g_h[dir][(s - 1) & 1];
#pragma unroll
            for (int q = 0; q < 4; q++) {
                const int sl = 4 * warp + q;
                if (sl == cta) continue;  // own slice written by gate stage
                unsigned f;
                do { f = ld_acquire(&g_flag[dir][sl]); } while (f < (unsigned)s);
                const float4* src = (const float4*)(hsrc + sl * 256);
                float4* dst = (float4*)(hsh + sl * 256);
                dst[lane]      = __ldcg(src + lane);
                dst[lane + 32] = __ldcg(src + lane + 32);
            }
        }
        __syncthreads();

        if (s > 0) {
            ull a00 = 0, a01 = 0, a02 = 0, a03 = 0;
            ull a10 = 0, a11 = 0, a12 = 0, a13 = 0;
            const float* hbase = hsh  + ks * 64 * 32 + 4 * bq;
            const float* wbase = Wsh2 + ks * 64 * 64 + 8 * cg;
#pragma unroll 8
            for (int k = 0; k < 64; k++) {
                ulonglong2 hv = *(const ulonglong2*)(hbase + k * 32);
                ulonglong2 w0 = *(const ulonglong2*)(wbase + k * 64);
                ulonglong2 w1 = *(const ulonglong2*)(wbase + k * 64 + 4);
                a00 = fma2(hv.x, w0.x, a00); a01 = fma2(hv.x, w0.y, a01);
                a02 = fma2(hv.x, w1.x, a02); a03 = fma2(hv.x, w1.y, a03);
                a10 = fma2(hv.y, w0.x, a10); a11 = fma2(hv.y, w0.y, a11);
                a12 = fma2(hv.y, w1.x, a12); a13 = fma2(hv.y, w1.y, a13);
            }
            const int c0 = cg * 4;
            const int bb = 4 * bq;
            *(float2*)&red[REDC(ks, c0 + 0, bb)]     = u2f(a00);
            *(float2*)&red[REDC(ks, c0 + 1, bb)]     = u2f(a01);
            *(float2*)&red[REDC(ks, c0 + 2, bb)]     = u2f(a02);
            *(float2*)&red[REDC(ks, c0 + 3, bb)]     = u2f(a03);
            *(float2*)&red[REDC(ks, c0 + 0, bb + 2)] = u2f(a10);
            *(float2*)&red[REDC(ks, c0 + 1, bb + 2)] = u2f(a11);
            *(float2*)&red[REDC(ks, c0 + 2, bb + 2)] = u2f(a12);
            *(float2*)&red[REDC(ks, c0 + 3, bb + 2)] = u2f(a13);
        }
        __syncthreads();

        if (gate_thread) {
            float z0 = x0, z1 = x1, z2 = x2, z3 = x3;
            if (s > 0) {
#pragma unroll
                for (int kk = 0; kk < NSPLIT; kk++) {
                    z0 += red[REDC(kk,  0 + jj_g, b_g)];
                    z1 += red[REDC(kk,  8 + jj_g, b_g)];
                    z2 += red[REDC(kk, 16 + jj_g, b_g)];
                    z3 += red[REDC(kk, 24 + jj_g, b_g)];
                }
            }
            const float ig = sigm(z0), fg = sigm(z1), og = sigm(z2), gg = tanh_(z3);
            cst = fmaf(fg, cst, ig * gg);
            const float hv = og * tanh_(cst);

            const int j = j0 + jj_g;
            __stcg(&g_h[dir][s & 1][j * B_ + b_g], hv);     // publish slice
            hsh[j * 32 + b_g] = hv;                         // own slice, local
            out[((size_t)b_g * T_ + t) * (2 * H_) + dir * H_ + j] = hv;
        }

        // all h stores done -> publish flag (no global barrier!)
        __syncthreads();
        if (tid == 0) {
            __threadfence();
            st_relaxed(&g_flag[dir][cta], (unsigned)(s + 1));
        }
    }
}

// ---------------------------------------------------------------------------
extern "C" void kernel_launch(void* const* d_in, const int* in_sizes, int n_in,
                              void* d_out, int out_size)
{
    const float* x   = (const float*)d_in[0];
    const float* Wfw = (const float*)d_in[1];
    const float* bfw = (const float*)d_in[2];
    const float* Wbw = (const float*)d_in[3];
    const float* bbw = (const float*)d_in[4];
    float* out = (float*)d_out;

    dim3 g(FOURH / 128, (B_ * T_) / 128, 2);
    gemm_xp<<<g, 256>>>(x, Wfw, bfw, Wbw, bbw);

    reset_flags<<<1, 128>>>();

    cudaFuncSetAttribute(lstm_kernel,
                         cudaFuncAttributeMaxDynamicSharedMemorySize, SMEM_BYTES);
    lstm_kernel<<<2 * NCTA, 512, SMEM_BYTES>>>(Wfw, Wbw, out);
}

// round 7
// speedup vs baseline: 1.6677x; 1.6677x over previous
#include <cuda_runtime.h>
#include <cstdint>

#define B_    32
#define T_    512
#define D_    512
#define H_    512
#define FOURH 2048
#define NCTA  64          // CTAs per direction

typedef unsigned long long ull;

// ---- scratch ----
__device__ float g_xp[2][(size_t)B_ * T_ * FOURH];   // input projections
__device__ float g_h[2][2][H_ * B_];                 // h state, TRANSPOSED [j][b]
__device__ unsigned g_flag[2][NCTA];                 // published-step counters

__device__ __forceinline__ float sigm(float x) { return 1.f / (1.f + __expf(-x)); }
__device__ __forceinline__ float tanh_(float x) { return 2.f / (1.f + __expf(-2.f * x)) - 1.f; }

__device__ __forceinline__ ull fma2(ull a, ull b, ull c) {
    ull d;
    asm("fma.rn.f32x2 %0, %1, %2, %3;" : "=l"(d) : "l"(a), "l"(b), "l"(c));
    return d;
}
union F2U { ull u; float2 f; };
__device__ __forceinline__ float2 u2f(ull v) { F2U x; x.u = v; return x.f; }

__device__ __forceinline__ unsigned ld_acquire(const unsigned* p) {
    unsigned v;
    asm volatile("ld.global.acquire.gpu.u32 %0, [%1];" : "=r"(v) : "l"(p));
    return v;
}
__device__ __forceinline__ void st_relaxed(unsigned* p, unsigned v) {
    asm volatile("st.global.relaxed.gpu.u32 [%0], %1;" :: "l"(p), "r"(v));
}

// ---------------------------------------------------------------------------
// Flag reset — runs before lstm each replay (flags must start at 0).
// ---------------------------------------------------------------------------
__global__ void reset_flags() {
    if (threadIdx.x < 2 * NCTA)
        ((unsigned*)g_flag)[threadIdx.x] = 0;
}

// ---------------------------------------------------------------------------
// Phase 1: xp GEMM — unchanged (R7 target: L1=96% wavefront-bound).
// ---------------------------------------------------------------------------
__global__ __launch_bounds__(256, 2) void gemm_xp(
    const float* __restrict__ x,
    const float* __restrict__ Wfw, const float* __restrict__ bfw,
    const float* __restrict__ Wbw, const float* __restrict__ bbw)
{
    const int dir = blockIdx.z;
    const float* __restrict__ Wd = dir ? Wbw : Wfw;
    const float* __restrict__ bd = dir ? bbw : bfw;
    float* __restrict__ C = g_xp[dir];

    __shared__ float As[2][8][256];
    __shared__ float Bs[2][8][128];

    const int tid = threadIdx.x;
    const int m0 = blockIdx.y * 128;
    const int n0 = blockIdx.x * 128;
    const int tx = tid & 15;
    const int ty = tid >> 4;

    const int arow = tid >> 1;
    const int ak4  = (tid & 1) * 4;
    const int bk = tid >> 5;
    const int bn = (tid & 31) * 4;

    const float* Ap = x  + (size_t)(m0 + arow) * D_ + ak4;
    const float* Bp = Wd + (size_t)bk * FOURH + n0 + bn;

    ull acc[8][4];
#pragma unroll
    for (int i = 0; i < 8; i++)
#pragma unroll
        for (int j = 0; j < 4; j++) acc[i][j] = 0ull;

    float4 av = *(const float4*)(Ap);
    float4 bv = *(const float4*)(Bp);

    for (int k0 = 0; k0 < D_; k0 += 8) {
        const int buf = (k0 >> 3) & 1;
        *(float2*)&As[buf][ak4 + 0][2 * arow] = make_float2(av.x, av.x);
        *(float2*)&As[buf][ak4 + 1][2 * arow] = make_float2(av.y, av.y);
        *(float2*)&As[buf][ak4 + 2][2 * arow] = make_float2(av.z, av.z);
        *(float2*)&As[buf][ak4 + 3][2 * arow] = make_float2(av.w, av.w);
        *(float4*)&Bs[buf][bk][bn] = bv;
        __syncthreads();

        if (k0 + 8 < D_) {
            av = *(const float4*)(Ap + k0 + 8);
            bv = *(const float4*)(Bp + (size_t)(k0 + 8) * FOURH);
        }

#pragma unroll
        for (int kk = 0; kk < 8; kk++) {
            const ulonglong2* ap2 = (const ulonglong2*)&As[buf][kk][ty * 16];
            const ulonglong2* bp2 = (const ulonglong2*)&Bs[buf][kk][tx * 8];
            ulonglong2 a01 = ap2[0], a23 = ap2[1], a45 = ap2[2], a67 = ap2[3];
            ulonglong2 b01 = bp2[0], b23 = bp2[1];
            ull aa[8] = {a01.x, a01.y, a23.x, a23.y, a45.x, a45.y, a67.x, a67.y};
            ull bb[4] = {b01.x, b01.y, b23.x, b23.y};
#pragma unroll
            for (int i = 0; i < 8; i++)
#pragma unroll
                for (int j = 0; j < 4; j++)
                    acc[i][j] = fma2(aa[i], bb[j], acc[i][j]);
        }
    }
    __syncthreads();

    float bias[8];
#pragma unroll
    for (int j = 0; j < 8; j++) bias[j] = bd[n0 + tx * 8 + j];

#pragma unroll
    for (int i = 0; i < 8; i++) {
        const size_t row = (size_t)(m0 + ty * 8 + i);
        float* cp = C + row * FOURH + n0 + tx * 8;
        float2 c0 = u2f(acc[i][0]), c1 = u2f(acc[i][1]);
        float2 c2 = u2f(acc[i][2]), c3 = u2f(acc[i][3]);
        float4 o0, o1;
        o0.x = c0.x + bias[0]; o0.y = c0.y + bias[1];
        o0.z = c1.x + bias[2]; o0.w = c1.y + bias[3];
        o1.x = c2.x + bias[4]; o1.y = c2.y + bias[5];
        o1.z = c3.x + bias[6]; o1.w = c3.y + bias[7];
        *(float4*)(cp + 0) = o0;
        *(float4*)(cp + 4) = o1;
    }
}

// ---------------------------------------------------------------------------
// Phase 2: persistent LSTM = R4 structure + min-flag sync (no atomics).
// Warp 0 polls all 64 flags (256B, 2 L2 sectors) with acquire loads; CTA
// released via syncthreads. Producers: stcg h -> fence -> relaxed flag store.
// Matvec: W-duplicated FFMA2 (FMA-bound, 4096 cyc/SM floor).
// ---------------------------------------------------------------------------
#define W2_FLOATS  (512 * 64)          // 32768 (duplicated W)
#define H_FLOATS   (512 * 32)          // 16384
#define RED_STRIDE 34
#define NSPLIT     8
#define REDC(ks, c, b) ((((ks) * 32 + (c)) * RED_STRIDE) + (b))
#define SMEM_BYTES ((W2_FLOATS + H_FLOATS + NSPLIT * 32 * RED_STRIDE) * 4)

__global__ __launch_bounds__(512) void lstm_kernel(
    const float* __restrict__ Wfw, const float* __restrict__ Wbw,
    float* __restrict__ out)
{
    extern __shared__ float sm[];
    float* Wsh2 = sm;                         // [k][64] : k*64 + 2c (dup pairs)
    float* hsh  = sm + W2_FLOATS;             // [k][32] : k*32 + b
    float* red  = sm + W2_FLOATS + H_FLOATS;  // [ks][c][34]

    const int tid = threadIdx.x;
    const int dir = blockIdx.x / NCTA;
    const int cta = blockIdx.x % NCTA;
    const int j0  = cta * 8;
    const float* __restrict__ W  = dir ? Wbw : Wfw;
    const float* __restrict__ xp = g_xp[dir];

    // Prologue: Wh slice -> smem duplicated pairs. c = gate*8 + jj.
    for (int idx = tid; idx < H_FLOATS; idx += 512) {
        const int k = idx >> 5, c = idx & 31;
        const int gate = c >> 3, jj = c & 7;
        const float v = W[(size_t)(D_ + k) * FOURH + gate * H_ + j0 + jj];
        Wsh2[k * 64 + 2 * c]     = v;
        Wsh2[k * 64 + 2 * c + 1] = v;
    }

    const int lane = tid & 31;
    // matvec roles: tid = ks*64 + cg*8 + bq
    const int bq = tid & 7;
    const int cg = (tid >> 3) & 7;
    const int ks = tid >> 6;
    // gate roles (first 256 threads)
    const int b_g = tid >> 3, jj_g = tid & 7;
    const bool gate_thread = (tid < 256);

    float cst = 0.f;
    __syncthreads();

    for (int s = 0; s < T_; s++) {
        const int t = dir ? (T_ - 1 - s) : s;

        float x0 = 0, x1 = 0, x2 = 0, x3 = 0;
        if (gate_thread) {
            const size_t xrow = ((size_t)b_g * T_ + t) * FOURH + j0 + jj_g;
            x0 = __ldg(xp + xrow + 0 * H_);
            x1 = __ldg(xp + xrow + 1 * H_);
            x2 = __ldg(xp + xrow + 2 * H_);
            x3 = __ldg(xp + xrow + 3 * H_);
        }

        if (s > 0) {
            // ---- min-flag wait: warp 0 only, coalesced 64-flag poll ----
            if (tid < 32) {
                const unsigned* fl = g_flag[dir];
                for (;;) {
                    const unsigned f0 = ld_acquire(fl + lane);
                    const unsigned f1 = ld_acquire(fl + lane + 32);
                    const bool ok = (f0 >= (unsigned)s) && (f1 >= (unsigned)s);
                    if (__all_sync(0xFFFFFFFFu, ok)) break;
                }
            }
            __syncthreads();

            // ---- stage h: plain copy g_h [j][b] -> hsh [k][b] ----
            const float4* src = (const float4*)(g_h[dir][(s - 1) & 1]);
            float4* dst = (float4*)hsh;
#pragma unroll 2
            for (int i = tid; i < H_FLOATS / 4; i += 512)
                dst[i] = __ldcg(src + i);
        }
        __syncthreads();

        if (s > 0) {
            ull a00 = 0, a01 = 0, a02 = 0, a03 = 0;
            ull a10 = 0, a11 = 0, a12 = 0, a13 = 0;
            const float* hbase = hsh  + ks * 64 * 32 + 4 * bq;
            const float* wbase = Wsh2 + ks * 64 * 64 + 8 * cg;
#pragma unroll 8
            for (int k = 0; k < 64; k++) {
                ulonglong2 hv = *(const ulonglong2*)(hbase + k * 32);
                ulonglong2 w0 = *(const ulonglong2*)(wbase + k * 64);
                ulonglong2 w1 = *(const ulonglong2*)(wbase + k * 64 + 4);
                a00 = fma2(hv.x, w0.x, a00); a01 = fma2(hv.x, w0.y, a01);
                a02 = fma2(hv.x, w1.x, a02); a03 = fma2(hv.x, w1.y, a03);
                a10 = fma2(hv.y, w0.x, a10); a11 = fma2(hv.y, w0.y, a11);
                a12 = fma2(hv.y, w1.x, a12); a13 = fma2(hv.y, w1.y, a13);
            }
            const int c0 = cg * 4;
            const int bb = 4 * bq;
            *(float2*)&red[REDC(ks, c0 + 0, bb)]     = u2f(a00);
            *(float2*)&red[REDC(ks, c0 + 1, bb)]     = u2f(a01);
            *(float2*)&red[REDC(ks, c0 + 2, bb)]     = u2f(a02);
            *(float2*)&red[REDC(ks, c0 + 3, bb)]     = u2f(a03);
            *(float2*)&red[REDC(ks, c0 + 0, bb + 2)] = u2f(a10);
            *(float2*)&red[REDC(ks, c0 + 1, bb + 2)] = u2f(a11);
            *(float2*)&red[REDC(ks, c0 + 2, bb + 2)] = u2f(a12);
            *(float2*)&red[REDC(ks, c0 + 3, bb + 2)] = u2f(a13);
        }
        __syncthreads();

        if (gate_thread) {
            float z0 = x0, z1 = x1, z2 = x2, z3 = x3;
            if (s > 0) {
#pragma unroll
                for (int kk = 0; kk < NSPLIT; kk++) {
                    z0 += red[REDC(kk,  0 + jj_g, b_g)];
                    z1 += red[REDC(kk,  8 + jj_g, b_g)];
                    z2 += red[REDC(kk, 16 + jj_g, b_g)];
                    z3 += red[REDC(kk, 24 + jj_g, b_g)];
                }
            }
            const float ig = sigm(z0), fg = sigm(z1), og = sigm(z2), gg = tanh_(z3);
            cst = fmaf(fg, cst, ig * gg);
            const float hv = og * tanh_(cst);

            const int j = j0 + jj_g;
            __stcg(&g_h[dir][s & 1][j * B_ + b_g], hv);     // publish slice
            out[((size_t)b_g * T_ + t) * (2 * H_) + dir * H_ + j] = hv;
        }

        // all h stores done -> release-publish flag (no atomics, no broadcast)
        __syncthreads();
        if (tid == 0) {
            __threadfence();
            st_relaxed(&g_flag[dir][cta], (unsigned)(s + 1));
        }
    }
}

// ---------------------------------------------------------------------------
extern "C" void kernel_launch(void* const* d_in, const int* in_sizes, int n_in,
                              void* d_out, int out_size)
{
    const float* x   = (const float*)d_in[0];
    const float* Wfw = (const float*)d_in[1];
    const float* bfw = (const float*)d_in[2];
    const float* Wbw = (const float*)d_in[3];
    const float* bbw = (const float*)d_in[4];
    float* out = (float*)d_out;

    dim3 g(FOURH / 128, (B_ * T_) / 128, 2);
    gemm_xp<<<g, 256>>>(x, Wfw, bfw, Wbw, bbw);

    reset_flags<<<1, 128>>>();

    cudaFuncSetAttribute(lstm_kernel,
                         cudaFuncAttributeMaxDynamicSharedMemorySize, SMEM_BYTES);
    lstm_kernel<<<2 * NCTA, 512, SMEM_BYTES>>>(Wfw, Wbw, out);
}

// round 8
// speedup vs baseline: 2.0792x; 1.2467x over previous
#include <cuda_runtime.h>
#include <cstdint>

#define B_    32
#define T_    512
#define D_    512
#define H_    512
#define FOURH 2048
#define NCTA  64          // CTAs per direction

typedef unsigned long long ull;

// ---- scratch ----
__device__ float g_xp[2][(size_t)B_ * T_ * FOURH];   // input projections
__device__ float g_h[2][2][H_ * B_];                 // h state, TRANSPOSED [j][b]
__device__ unsigned g_count[2];
__device__ unsigned g_gen[2];

__device__ __forceinline__ float sigm(float x) { return 1.f / (1.f + __expf(-x)); }
__device__ __forceinline__ float tanh_(float x) { return 2.f / (1.f + __expf(-2.f * x)) - 1.f; }

__device__ __forceinline__ ull fma2(ull a, ull b, ull c) {
    ull d;
    asm("fma.rn.f32x2 %0, %1, %2, %3;" : "=l"(d) : "l"(a), "l"(b), "l"(c));
    return d;
}
union F2U { ull u; float2 f; };
__device__ __forceinline__ float2 u2f(ull v) { F2U x; x.u = v; return x.f; }
__device__ __forceinline__ ull dupf(float v) { F2U x; x.f = make_float2(v, v); return x.u; }

// ---------------------------------------------------------------------------
// Phase 1: xp GEMM, retiled for FMA-bound.
// 128x128x8 tile, 256 threads, 16m x 4n per thread.
//   tx = tid&31 (n-group), ty = tid>>5 (m-group) == warp id
//   -> A LDS.128 are warp-uniform broadcasts (1 wavefront each)
//   -> B loaded natural (1 LDS.128, 4 wf), duplicated into f32x2 via regs
// Per warp per kk: 8 crossbar wf vs 64 FMA2-issue slots -> FMA-bound.
// ---------------------------------------------------------------------------
__global__ __launch_bounds__(256, 2) void gemm_xp(
    const float* __restrict__ x,
    const float* __restrict__ Wfw, const float* __restrict__ bfw,
    const float* __restrict__ Wbw, const float* __restrict__ bbw)
{
    const int dir = blockIdx.z;
    const float* __restrict__ Wd = dir ? Wbw : Wfw;
    const float* __restrict__ bd = dir ? bbw : bfw;
    float* __restrict__ C = g_xp[dir];

    __shared__ float As[2][8][128];   // [k][m] natural
    __shared__ float Bs[2][8][128];   // [k][n] natural

    const int tid = threadIdx.x;
    const int m0 = blockIdx.y * 128;
    const int n0 = blockIdx.x * 128;
    const int tx = tid & 31;          // n-group: 4 n each
    const int ty = tid >> 5;          // m-group: 16 m each (== warp)

    // A tile load/transpose: thread -> (row, 4 k's)
    const int arow = tid >> 1;
    const int ak4  = (tid & 1) * 4;
    // B tile load: thread -> (k, 4 n's)
    const int bk = tid >> 5;
    const int bn = (tid & 31) * 4;

    const float* Ap = x  + (size_t)(m0 + arow) * D_ + ak4;
    const float* Bp = Wd + (size_t)bk * FOURH + n0 + bn;

    ull acc[8][4];   // [m-pair][n]
#pragma unroll
    for (int p = 0; p < 8; p++)
#pragma unroll
        for (int j = 0; j < 4; j++) acc[p][j] = 0ull;

    float4 av = *(const float4*)(Ap);
    float4 bv = *(const float4*)(Bp);

    for (int k0 = 0; k0 < D_; k0 += 8) {
        const int buf = (k0 >> 3) & 1;
        As[buf][ak4 + 0][arow] = av.x;
        As[buf][ak4 + 1][arow] = av.y;
        As[buf][ak4 + 2][arow] = av.z;
        As[buf][ak4 + 3][arow] = av.w;
        *(float4*)&Bs[buf][bk][bn] = bv;
        __syncthreads();

        if (k0 + 8 < D_) {
            av = *(const float4*)(Ap + k0 + 8);
            bv = *(const float4*)(Bp + (size_t)(k0 + 8) * FOURH);
        }

#pragma unroll
        for (int kk = 0; kk < 8; kk++) {
            // A: 16 m = 8 f32x2 pairs, warp-uniform addresses (broadcast)
            const ulonglong2* ap2 = (const ulonglong2*)&As[buf][kk][ty * 16];
            ulonglong2 A0 = ap2[0], A1 = ap2[1], A2 = ap2[2], A3 = ap2[3];
            ull am[8] = {A0.x, A0.y, A1.x, A1.y, A2.x, A2.y, A3.x, A3.y};
            // B: 4 n natural, duplicate in registers (alu pipe)
            float4 b4 = *(const float4*)&Bs[buf][kk][tx * 4];
            ull bdp[4] = {dupf(b4.x), dupf(b4.y), dupf(b4.z), dupf(b4.w)};
#pragma unroll
            for (int p = 0; p < 8; p++)
#pragma unroll
                for (int j = 0; j < 4; j++)
                    acc[p][j] = fma2(am[p], bdp[j], acc[p][j]);
        }
    }
    __syncthreads();

    float bias[4];
#pragma unroll
    for (int j = 0; j < 4; j++) bias[j] = bd[n0 + tx * 4 + j];

#pragma unroll
    for (int p = 0; p < 8; p++) {
        float2 c0 = u2f(acc[p][0]), c1 = u2f(acc[p][1]);
        float2 c2 = u2f(acc[p][2]), c3 = u2f(acc[p][3]);
        const size_t r0 = (size_t)(m0 + ty * 16 + 2 * p);
        float* cp0 = C + r0 * FOURH + n0 + tx * 4;
        float* cp1 = cp0 + FOURH;
        float4 o0, o1;
        o0.x = c0.x + bias[0]; o0.y = c1.x + bias[1];
        o0.z = c2.x + bias[2]; o0.w = c3.x + bias[3];
        o1.x = c0.y + bias[0]; o1.y = c1.y + bias[1];
        o1.z = c2.y + bias[2]; o1.w = c3.y + bias[3];
        *(float4*)cp0 = o0;
        *(float4*)cp1 = o1;
    }
}

// ---------------------------------------------------------------------------
// Phase 2: persistent LSTM. R4 structure + atomic barrier, but NO staging:
// matvec reads h directly from L2 via __ldcg (g_h layout [j][b] == [k][b]).
// smem: Wsh2 128KB resident + red 34.8KB only.
// ---------------------------------------------------------------------------
#define W2_FLOATS  (512 * 64)          // 32768 (duplicated W)
#define RED_STRIDE 34
#define NSPLIT     8
#define REDC(ks, c, b) ((((ks) * 32 + (c)) * RED_STRIDE) + (b))
#define SMEM_BYTES ((W2_FLOATS + NSPLIT * 32 * RED_STRIDE) * 4)

union LD4 { float4 f; ulonglong2 u; };

__global__ __launch_bounds__(512) void lstm_kernel(
    const float* __restrict__ Wfw, const float* __restrict__ Wbw,
    float* __restrict__ out)
{
    extern __shared__ float sm[];
    float* Wsh2 = sm;                 // [k][64] : k*64 + 2c (dup pairs)
    float* red  = sm + W2_FLOATS;     // [ks][c][34]

    const int tid = threadIdx.x;
    const int dir = blockIdx.x / NCTA;
    const int cta = blockIdx.x % NCTA;
    const int j0  = cta * 8;
    const float* __restrict__ W  = dir ? Wbw : Wfw;
    const float* __restrict__ xp = g_xp[dir];

    // Prologue: Wh slice -> smem duplicated pairs. c = gate*8 + jj.
    for (int idx = tid; idx < 512 * 32; idx += 512) {
        const int k = idx >> 5, c = idx & 31;
        const int gate = c >> 3, jj = c & 7;
        const float v = W[(size_t)(D_ + k) * FOURH + gate * H_ + j0 + jj];
        Wsh2[k * 64 + 2 * c]     = v;
        Wsh2[k * 64 + 2 * c + 1] = v;
    }

    // matvec roles: tid = ks*64 + cg*8 + bq
    const int bq = tid & 7;
    const int cg = (tid >> 3) & 7;
    const int ks = tid >> 6;
    // gate roles (first 256 threads)
    const int b_g = tid >> 3, jj_g = tid & 7;
    const bool gate_thread = (tid < 256);

    float cst = 0.f;
    __syncthreads();

    for (int s = 0; s < T_; s++) {
        const int t = dir ? (T_ - 1 - s) : s;

        float x0 = 0, x1 = 0, x2 = 0, x3 = 0;
        if (gate_thread) {
            const size_t xrow = ((size_t)b_g * T_ + t) * FOURH + j0 + jj_g;
            x0 = __ldg(xp + xrow + 0 * H_);
            x1 = __ldg(xp + xrow + 1 * H_);
            x2 = __ldg(xp + xrow + 2 * H_);
            x3 = __ldg(xp + xrow + 3 * H_);
        }

        if (s > 0) {
            // matvec: h from L2 directly (ldcg, bypass stale L1)
            ull a00 = 0, a01 = 0, a02 = 0, a03 = 0;
            ull a10 = 0, a11 = 0, a12 = 0, a13 = 0;
            const float* hbase = g_h[dir][(s - 1) & 1] + ks * 64 * 32 + 4 * bq;
            const float* wbase = Wsh2 + ks * 64 * 64 + 8 * cg;
#pragma unroll 8
            for (int k = 0; k < 64; k++) {
                LD4 hv; hv.f = __ldcg((const float4*)(hbase + k * 32));
                ulonglong2 w0 = *(const ulonglong2*)(wbase + k * 64);
                ulonglong2 w1 = *(const ulonglong2*)(wbase + k * 64 + 4);
                a00 = fma2(hv.u.x, w0.x, a00); a01 = fma2(hv.u.x, w0.y, a01);
                a02 = fma2(hv.u.x, w1.x, a02); a03 = fma2(hv.u.x, w1.y, a03);
                a10 = fma2(hv.u.y, w0.x, a10); a11 = fma2(hv.u.y, w0.y, a11);
                a12 = fma2(hv.u.y, w1.x, a12); a13 = fma2(hv.u.y, w1.y, a13);
            }
            const int c0 = cg * 4;
            const int bb = 4 * bq;
            *(float2*)&red[REDC(ks, c0 + 0, bb)]     = u2f(a00);
            *(float2*)&red[REDC(ks, c0 + 1, bb)]     = u2f(a01);
            *(float2*)&red[REDC(ks, c0 + 2, bb)]     = u2f(a02);
            *(float2*)&red[REDC(ks, c0 + 3, bb)]     = u2f(a03);
            *(float2*)&red[REDC(ks, c0 + 0, bb + 2)] = u2f(a10);
            *(float2*)&red[REDC(ks, c0 + 1, bb + 2)] = u2f(a11);
            *(float2*)&red[REDC(ks, c0 + 2, bb + 2)] = u2f(a12);
            *(float2*)&red[REDC(ks, c0 + 3, bb + 2)] = u2f(a13);
        }
        __syncthreads();

        if (gate_thread) {
            float z0 = x0, z1 = x1, z2 = x2, z3 = x3;
            if (s > 0) {
#pragma unroll
                for (int kk = 0; kk < NSPLIT; kk++) {
                    z0 += red[REDC(kk,  0 + jj_g, b_g)];
                    z1 += red[REDC(kk,  8 + jj_g, b_g)];
                    z2 += red[REDC(kk, 16 + jj_g, b_g)];
                    z3 += red[REDC(kk, 24 + jj_g, b_g)];
                }
            }
            const float ig = sigm(z0), fg = sigm(z1), og = sigm(z2), gg = tanh_(z3);
            cst = fmaf(fg, cst, ig * gg);
            const float hv = og * tanh_(cst);

            const int j = j0 + jj_g;
            __stcg(&g_h[dir][s & 1][j * B_ + b_g], hv);
            out[((size_t)b_g * T_ + t) * (2 * H_) + dir * H_ + j] = hv;
        }

        // collect all h-publishes, then global barrier (R4 proven best)
        __syncthreads();
        if (tid == 0) {
            __threadfence();
            const unsigned gen = *(volatile unsigned*)&g_gen[dir];
            const unsigned old = atomicAdd(&g_count[dir], 1);
            if (old == NCTA - 1) {
                atomicExch(&g_count[dir], 0);
                __threadfence();
                atomicAdd(&g_gen[dir], 1);
            } else {
                while (*(volatile unsigned*)&g_gen[dir] == gen) { }
            }
            __threadfence();
        }
        __syncthreads();
    }
}

// ---------------------------------------------------------------------------
extern "C" void kernel_launch(void* const* d_in, const int* in_sizes, int n_in,
                              void* d_out, int out_size)
{
    const float* x   = (const float*)d_in[0];
    const float* Wfw = (const float*)d_in[1];
    const float* bfw = (const float*)d_in[2];
    const float* Wbw = (const float*)d_in[3];
    const float* bbw = (const float*)d_in[4];
    float* out = (float*)d_out;

    dim3 g(FOURH / 128, (B_ * T_) / 128, 2);
    gemm_xp<<<g, 256>>>(x, Wfw, bfw, Wbw, bbw);

    cudaFuncSetAttribute(lstm_kernel,
                         cudaFuncAttributeMaxDynamicSharedMemorySize, SMEM_BYTES);
    lstm_kernel<<<2 * NCTA, 512, SMEM_BYTES>>>(Wfw, Wbw, out);
}

// round 10
// speedup vs baseline: 2.3178x; 1.1148x over previous
#include <cuda_runtime.h>
#include <cstdint>

#define B_    32
#define T_    512
#define D_    512
#define H_    512
#define FOURH 2048
#define NCTA  64           // LSTM CTAs per direction
#define NLSTM 128          // total LSTM CTAs
#define NWORK 168          // GEMM worker CTAs
#define NTILES 4096        // 4 bands x 2 dirs x 32 b x 16 n

typedef unsigned long long ull;

// ---- scratch ----
__device__ float g_xp[2][(size_t)B_ * T_ * FOURH];
__device__ float g_h[2][2][H_ * B_];           // [dir][parity][j*32+b]
__device__ unsigned g_count[2], g_gen[2];      // LSTM barrier (self-resetting)
__device__ unsigned g_work;                    // GEMM tile work counter
__device__ unsigned g_band[2][4];              // band completion counters

__device__ __forceinline__ float sigm(float x) { return 1.f / (1.f + __expf(-x)); }
__device__ __forceinline__ float tanh_(float x) { return 2.f / (1.f + __expf(-2.f * x)) - 1.f; }

__device__ __forceinline__ ull fma2(ull a, ull b, ull c) {
    ull d;
    asm("fma.rn.f32x2 %0, %1, %2, %3;" : "=l"(d) : "l"(a), "l"(b), "l"(c));
    return d;
}
union F2U { ull u; float2 f; };
__device__ __forceinline__ float2 u2f(ull v) { F2U x; x.u = v; return x.f; }
__device__ __forceinline__ ull dupf(float v) {
    ull d;
    asm("mov.b64 %0, {%1, %1};" : "=l"(d) : "f"(v));
    return d;
}
__device__ __forceinline__ unsigned ld_acquire(const unsigned* p) {
    unsigned v;
    asm volatile("ld.global.acquire.gpu.u32 %0, [%1];" : "=r"(v) : "l"(p));
    return v;
}
union LD4 { float4 f; ulonglong2 u; };

__global__ void reset_counters() {
    if (threadIdx.x == 0) g_work = 0;
    if (threadIdx.x < 8) ((unsigned*)g_band)[threadIdx.x] = 0;
}

// ---------------------------------------------------------------------------
// smem: LSTM role: Wsh [512][32] (64KB) + red [8][32][34] (34KB)
//       GEMM role: As/Bs double-buffered (16KB) + ticket slot (overlaid)
// Total 100,352 B -> 2 CTAs/SM (296 CTAs all wave-1 resident).
// ---------------------------------------------------------------------------
#define W_FLOATS   (512 * 32)
#define RED_STRIDE 34
#define NSPLIT     8
#define RED2(ks, b, c) ((((ks) * 32 + (b)) * RED_STRIDE) + (c))
#define SMEM_BYTES ((W_FLOATS + NSPLIT * 32 * RED_STRIDE) * 4)

// ======================= LSTM role (blockIdx < 128) ========================
__device__ __forceinline__ void lstm_role(
    float* sm, const float* __restrict__ Wfw, const float* __restrict__ Wbw,
    float* __restrict__ out)
{
    float* Wsh = sm;                  // [k][c] natural: k*32 + c
    float* red = sm + W_FLOATS;       // [ks][b][34] + c

    const int tid = threadIdx.x;
    const int dir = blockIdx.x / NCTA;
    const int cta = blockIdx.x % NCTA;
    const int j0  = cta * 8;
    const float* __restrict__ W  = dir ? Wbw : Wfw;
    const float* __restrict__ xp = g_xp[dir];

    // Prologue: Wh slice -> smem natural [k][c], c = gate*8 + jj.
    for (int idx = tid; idx < W_FLOATS; idx += 512) {
        const int k = idx >> 5, c = idx & 31;
        const int gate = c >> 3, jj = c & 7;
        Wsh[k * 32 + c] = W[(size_t)(D_ + k) * FOURH + gate * H_ + j0 + jj];
    }

    // matvec roles: tid = ks*64 + cg*8 + bq
    const int bq = tid & 7;
    const int cg = (tid >> 3) & 7;
    const int ks = tid >> 6;
    // gate roles (first 256 threads)
    const int b_g = tid >> 3, jj_g = tid & 7;
    const bool gate_thread = (tid < 256);

    float cst = 0.f;
    __syncthreads();

    for (int s = 0; s < T_; s++) {
        const int t = dir ? (T_ - 1 - s) : s;

        // band gate: xp for t-band (s>>7) must be complete
        if ((s & 127) == 0) {
            if (tid == 0) {
                const unsigned* bp = &g_band[dir][s >> 7];
                while (ld_acquire(bp) < 512u) { }
            }
            __syncthreads();
        }

        float x0 = 0, x1 = 0, x2 = 0, x3 = 0;
        if (gate_thread) {
            const size_t xrow = ((size_t)b_g * T_ + t) * FOURH + j0 + jj_g;
            x0 = __ldg(xp + xrow + 0 * H_);
            x1 = __ldg(xp + xrow + 1 * H_);
            x2 = __ldg(xp + xrow + 2 * H_);
            x3 = __ldg(xp + xrow + 3 * H_);
        }

        if (s > 0) {
            ull a0x = 0, a0y = 0, a1x = 0, a1y = 0;
            ull a2x = 0, a2y = 0, a3x = 0, a3y = 0;
            const float* hbase = g_h[dir][(s - 1) & 1] + ks * 64 * 32 + 4 * bq;
            const float* wbase = Wsh + ks * 64 * 32 + 4 * cg;
#pragma unroll 8
            for (int k = 0; k < 64; k++) {
                LD4 hv; hv.f = __ldcg((const float4*)(hbase + k * 32));
                ulonglong2 wv = *(const ulonglong2*)(wbase + k * 32);
                const ull h0 = dupf(hv.f.x), h1 = dupf(hv.f.y);
                const ull h2 = dupf(hv.f.z), h3 = dupf(hv.f.w);
                a0x = fma2(h0, wv.x, a0x); a0y = fma2(h0, wv.y, a0y);
                a1x = fma2(h1, wv.x, a1x); a1y = fma2(h1, wv.y, a1y);
                a2x = fma2(h2, wv.x, a2x); a2y = fma2(h2, wv.y, a2y);
                a3x = fma2(h3, wv.x, a3x); a3y = fma2(h3, wv.y, a3y);
            }
            const int c0 = 4 * cg;
            const int bb = 4 * bq;
            *(float2*)&red[RED2(ks, bb + 0, c0)]     = u2f(a0x);
            *(float2*)&red[RED2(ks, bb + 0, c0 + 2)] = u2f(a0y);
            *(float2*)&red[RED2(ks, bb + 1, c0)]     = u2f(a1x);
            *(float2*)&red[RED2(ks, bb + 1, c0 + 2)] = u2f(a1y);
            *(float2*)&red[RED2(ks, bb + 2, c0)]     = u2f(a2x);
            *(float2*)&red[RED2(ks, bb + 2, c0 + 2)] = u2f(a2y);
            *(float2*)&red[RED2(ks, bb + 3, c0)]     = u2f(a3x);
            *(float2*)&red[RED2(ks, bb + 3, c0 + 2)] = u2f(a3y);
        }
        __syncthreads();

        if (gate_thread) {
            float z0 = x0, z1 = x1, z2 = x2, z3 = x3;
            if (s > 0) {
#pragma unroll
                for (int kk = 0; kk < NSPLIT; kk++) {
                    z0 += red[RED2(kk, b_g,  0 + jj_g)];
                    z1 += red[RED2(kk, b_g,  8 + jj_g)];
                    z2 += red[RED2(kk, b_g, 16 + jj_g)];
                    z3 += red[RED2(kk, b_g, 24 + jj_g)];
                }
            }
            const float ig = sigm(z0), fg = sigm(z1), og = sigm(z2), gg = tanh_(z3);
            cst = fmaf(fg, cst, ig * gg);
            const float hv = og * tanh_(cst);

            const int j = j0 + jj_g;
            __stcg(&g_h[dir][s & 1][j * B_ + b_g], hv);
            out[((size_t)b_g * T_ + t) * (2 * H_) + dir * H_ + j] = hv;
        }

        __syncthreads();

        if (tid == 0) {
            __threadfence();
            const unsigned gen = *(volatile unsigned*)&g_gen[dir];
            const unsigned old = atomicAdd(&g_count[dir], 1);
            if (old == NCTA - 1) {
                atomicExch(&g_count[dir], 0);
                __threadfence();
                atomicAdd(&g_gen[dir], 1);
            } else {
                while (*(volatile unsigned*)&g_gen[dir] == gen) { }
            }
            __threadfence();
        }
        __syncthreads();
    }
}

// ======================= GEMM worker role (blockIdx >= 128) ================
__device__ __forceinline__ void gemm_role(
    float* sm, const float* __restrict__ x,
    const float* __restrict__ Wfw, const float* __restrict__ bfw,
    const float* __restrict__ Wbw, const float* __restrict__ bbw)
{
    float* As = sm;                       // [2][8][128]
    float* Bs = sm + 2048;                // [2][8][128]
    unsigned* ticket = (unsigned*)(sm + 4096);  // CTA-uniform tile id

    const int tid = threadIdx.x;
    // loaders
    const int ar  = tid >> 2;
    const int ac2 = (tid & 3) * 2;
    const int bk  = tid >> 6;
    const int bn2 = (tid & 63) * 2;
    // compute
    const int tx = tid & 31;
    const int ty = tid >> 5;

    for (;;) {
        // -------- FIX: CTA-uniform work stealing (one ticket per CTA) ------
        if (tid == 0) *ticket = atomicAdd(&g_work, 1u);
        __syncthreads();
        const unsigned id = *ticket;      // uniform -> uniform break
        if (id >= NTILES) break;

        const int lb   = id >> 10;
        const int rem  = id & 1023;
        const int dir  = rem >> 9;
        const int rem2 = rem & 511;
        const int bi   = rem2 >> 4;
        const int ni   = rem2 & 15;
        const int tband = dir ? (3 - lb) : lb;
        const int m0 = bi * T_ + tband * 128;
        const int n0 = ni * 128;
        const float* __restrict__ Wd = dir ? Wbw : Wfw;
        const float* __restrict__ bd = dir ? bbw : bfw;
        float* __restrict__ C = g_xp[dir];

        const float* Ap = x  + (size_t)(m0 + ar) * D_ + ac2;
        const float* Bp = Wd + (size_t)bk * FOURH + n0 + bn2;

        ull acc[4][4];
#pragma unroll
        for (int p = 0; p < 4; p++)
#pragma unroll
            for (int j = 0; j < 4; j++) acc[p][j] = 0ull;

        float2 av = *(const float2*)(Ap);
        float2 bv = *(const float2*)(Bp);

        for (int k0 = 0; k0 < D_; k0 += 8) {
            const int buf = (k0 >> 3) & 1;
            float* Asb = As + buf * 1024;
            float* Bsb = Bs + buf * 1024;
            Asb[(ac2 + 0) * 128 + ar] = av.x;
            Asb[(ac2 + 1) * 128 + ar] = av.y;
            *(float2*)&Bsb[bk * 128 + bn2] = bv;
            __syncthreads();

            if (k0 + 8 < D_) {
                av = *(const float2*)(Ap + k0 + 8);
                bv = *(const float2*)(Bp + (size_t)(k0 + 8) * FOURH);
            }

#pragma unroll
            for (int kk = 0; kk < 8; kk++) {
                const ulonglong2* ap2 =
                    (const ulonglong2*)&Asb[kk * 128 + ty * 8];
                ulonglong2 A0 = ap2[0], A1 = ap2[1];
                ull am[4] = {A0.x, A0.y, A1.x, A1.y};
                float4 b4 = *(const float4*)&Bsb[kk * 128 + tx * 4];
                ull bdp[4] = {dupf(b4.x), dupf(b4.y), dupf(b4.z), dupf(b4.w)};
#pragma unroll
                for (int p = 0; p < 4; p++)
#pragma unroll
                    for (int j = 0; j < 4; j++)
                        acc[p][j] = fma2(am[p], bdp[j], acc[p][j]);
            }
            __syncthreads();
        }

        float bias[4];
#pragma unroll
        for (int j = 0; j < 4; j++) bias[j] = bd[n0 + tx * 4 + j];

#pragma unroll
        for (int p = 0; p < 4; p++) {
            float2 c0 = u2f(acc[p][0]), c1 = u2f(acc[p][1]);
            float2 c2 = u2f(acc[p][2]), c3 = u2f(acc[p][3]);
            const size_t r0 = (size_t)(m0 + ty * 8 + 2 * p);
            float* cp0 = C + r0 * FOURH + n0 + tx * 4;
            float* cp1 = cp0 + FOURH;
            float4 o0, o1;
            o0.x = c0.x + bias[0]; o0.y = c1.x + bias[1];
            o0.z = c2.x + bias[2]; o0.w = c3.x + bias[3];
            o1.x = c0.y + bias[0]; o1.y = c1.y + bias[1];
            o1.z = c2.y + bias[2]; o1.w = c3.y + bias[3];
            *(float4*)cp0 = o0;
            *(float4*)cp1 = o1;
        }
        __syncthreads();   // fences smem (and ticket) for next iteration

        if (tid == 0) {
            __threadfence();
            atomicAdd(&g_band[dir][lb], 1u);
        }
    }
}

// ======================= unified persistent kernel =========================
__global__ __launch_bounds__(512, 2) void fused_kernel(
    const float* __restrict__ x,
    const float* __restrict__ Wfw, const float* __restrict__ bfw,
    const float* __restrict__ Wbw, const float* __restrict__ bbw,
    float* __restrict__ out)
{
    extern __shared__ float sm[];
    if (blockIdx.x < NLSTM) lstm_role(sm, Wfw, Wbw, out);
    else                    gemm_role(sm, x, Wfw, bfw, Wbw, bbw);
}

// ---------------------------------------------------------------------------
extern "C" void kernel_launch(void* const* d_in, const int* in_sizes, int n_in,
                              void* d_out, int out_size)
{
    const float* x   = (const float*)d_in[0];
    const float* Wfw = (const float*)d_in[1];
    const float* bfw = (const float*)d_in[2];
    const float* Wbw = (const float*)d_in[3];
    const float* bbw = (const float*)d_in[4];
    float* out = (float*)d_out;

    reset_counters<<<1, 32>>>();

    cudaFuncSetAttribute(fused_kernel,
                         cudaFuncAttributeMaxDynamicSharedMemorySize, SMEM_BYTES);
    fused_kernel<<<NLSTM + NWORK, 512, SMEM_BYTES>>>(x, Wfw, bfw, Wbw, bbw, out);
}